// round 11
// baseline (speedup 1.0000x reference)
#include <cuda_runtime.h>
#include <cstdint>

#define NN 50000
#define NPAD 50048
#define EE 800000
#define ETOT (EE + NN)

// ---------------- scratch ----------------
__device__ float  g_z[(size_t)NPAD * 1024];   // rows >= NN stay zero (never written)
__device__ float  g_xh_mean[(size_t)NN * 64];
__device__ float4 g_srcA[NN * 2];   // [2n]=cov logits (src), [2n+1]=mean logits (src)
__device__ float4 g_dstA[NN * 2];
__device__ float  g_Wc2[256 * 256];
__device__ float  g_BT[256 * 1024];
__device__ float  g_Wfold_mean[16 * 64];
__device__ float4 g_wsrc_cov[256], g_wdst_cov[256];
__device__ float4 g_wsrc_mean[16], g_wdst_mean[16];
__device__ float  g_bias_cov_out[256];
__device__ float  g_bias_mean_out[16];
__device__ int    g_counts[NN];
__device__ int    g_offsets[NN + 1];
__device__ int    g_cursor[NN];
__device__ int    g_csr_src[ETOT];
__device__ float4 g_coef[(size_t)ETOT * 2];  // [2e]=cov numerators, [2e+1]=mean numerators

__device__ __forceinline__ float lrelu(float x) { return x > 0.f ? x : 0.2f * x; }

__device__ __forceinline__ float to_tf32(float x) {
    float r;
    asm("cvt.rna.tf32.f32 %0, %1;" : "=f"(r) : "f"(x));
    return r;
}

__device__ __forceinline__ void wred_sum4(float4& v) {
#pragma unroll
    for (int o = 16; o; o >>= 1) {
        v.x += __shfl_xor_sync(0xffffffffu, v.x, o);
        v.y += __shfl_xor_sync(0xffffffffu, v.y, o);
        v.z += __shfl_xor_sync(0xffffffffu, v.z, o);
        v.w += __shfl_xor_sync(0xffffffffu, v.w, o);
    }
}

// ---------------- cp.async / mma helpers ----------------
__device__ __forceinline__ uint32_t smem_u32(const void* p) {
    uint32_t a;
    asm("{ .reg .u64 tmp; cvta.to.shared.u64 tmp, %1; cvt.u32.u64 %0, tmp; }" : "=r"(a) : "l"(p));
    return a;
}
__device__ __forceinline__ void cp16(uint32_t dst, const void* src) {
    asm volatile("cp.async.cg.shared.global [%0], [%1], 16;" :: "r"(dst), "l"(src));
}
#define CP_COMMIT() asm volatile("cp.async.commit_group;" ::: "memory")

#define MMA_TF32(d, a, b) \
    asm volatile("mma.sync.aligned.m16n8k8.row.col.f32.tf32.tf32.f32 " \
        "{%0,%1,%2,%3}, {%4,%5,%6,%7}, {%8,%9}, {%0,%1,%2,%3};" \
        : "+f"((d)[0]), "+f"((d)[1]), "+f"((d)[2]), "+f"((d)[3]) \
        : "r"((a)[0]), "r"((a)[1]), "r"((a)[2]), "r"((a)[3]), "r"((b)[0]), "r"((b)[1]))

// ================= device-side phase bodies =================

__device__ void body_prep_mean(const float* fmW1, const float* fmW2,
                               const float* fmb1, const float* fmb2,
                               const float* bias_mean, const float* W_mean,
                               const float* att_src, const float* att_dst) {
    __shared__ float Wm2s[16][16];
    int t = threadIdx.x;
    {
        int r = t >> 4, c = t & 15;
        float s = 0.f;
        for (int k = 0; k < 16; k++) s += fmW1[r * 16 + k] * fmW2[k * 16 + c];
        Wm2s[r][c] = s;
    }
    if (t < 128) {
        int sd = t >> 6, rem = t & 63, r = rem >> 2, h = rem & 3;
        const float* att = sd ? att_dst : att_src;
        float s = 0.f;
        for (int j = 0; j < 16; j++) s += W_mean[r * 64 + h * 16 + j] * att[h * 16 + j];
        float* dstp = sd ? (float*)g_wdst_mean : (float*)g_wsrc_mean;
        dstp[r * 4 + h] = s;
    }
    __syncthreads();
    if (t < 16) {
        float b = fmb2[t];
        for (int k = 0; k < 16; k++)
            b += bias_mean[k] * Wm2s[k][t] + fmb1[k] * fmW2[k * 16 + t];
        g_bias_mean_out[t] = b;
    }
    for (int o = t; o < 1024; o += 256) {
        int r = o >> 6, hc = o & 63, h = hc >> 4, c = hc & 15;
        float s = 0.f;
        for (int j = 0; j < 16; j++) s += W_mean[r * 64 + h * 16 + j] * Wm2s[j][c];
        g_Wfold_mean[o] = s;
    }
}

__device__ void body_Wc2(int vb, const float* W1, const float* W2) {
    int r = vb, c = threadIdx.x;
    float s = 0.f;
    for (int k = 0; k < 256; k++) s += W1[r * 256 + k] * W2[k * 256 + c];
    g_Wc2[r * 256 + c] = s;
}

__device__ void body_att_cov(int vb, const float* W_cov, const float* att_src,
                             const float* att_dst) {
    int o = vb * 256 + threadIdx.x;
    int sd = o >> 10, rem = o & 1023, r = rem >> 2, h = rem & 3;
    const float* att = sd ? att_dst : att_src;
    const float* wrow = W_cov + (size_t)r * 1024 + h * 256;
    float s = 0.f;
    for (int j = 0; j < 256; j++) s += wrow[j] * att[h * 256 + j];
    float* dstp = sd ? (float*)g_wdst_cov : (float*)g_wsrc_cov;
    dstp[r * 4 + h] = s;
}

__device__ void body_init_counts(int vb) {
    int i = vb * 256 + threadIdx.x;
    if (i < NN) g_counts[i] = 1;
}

__device__ void body_bias_cov(const float* bias_cov, const float* fb1,
                              const float* fW2, const float* fb2) {
    int c = threadIdx.x;
    float b = fb2[c];
    for (int k = 0; k < 256; k++)
        b += bias_cov[k] * g_Wc2[k * 256 + c] + fb1[k] * fW2[k * 256 + c];
    g_bias_cov_out[c] = b;
}

__device__ void body_Wfold_cov(int vb, const float* W_cov) {
    __shared__ float wc2s[32][256];
    __shared__ float wr[4][256];
    int seg = vb & 3, r0 = (vb >> 2) * 4;
    int t = threadIdx.x;
    float acc[4];
#pragma unroll
    for (int i = 0; i < 4; i++) acc[i] = 0.f;
#pragma unroll
    for (int i = 0; i < 4; i++)
        wr[i][t] = W_cov[(size_t)(r0 + i) * 1024 + seg * 256 + t];
    __syncthreads();
    for (int j0 = 0; j0 < 256; j0 += 32) {
        for (int i = 0; i < 32; i++)
            wc2s[i][t] = g_Wc2[(size_t)(j0 + i) * 256 + t];
        __syncthreads();
#pragma unroll
        for (int jj = 0; jj < 32; jj++) {
            float b = wc2s[jj][t];
#pragma unroll
            for (int i = 0; i < 4; i++) acc[i] += wr[i][j0 + jj] * b;
        }
        __syncthreads();
    }
#pragma unroll
    for (int i = 0; i < 4; i++)
        g_BT[(size_t)t * 1024 + seg * 256 + r0 + i] = to_tf32(0.25f * acc[i]);
}

__device__ void body_hist(int vb, const int* ei) {
    int e = vb * 256 + threadIdx.x;
    if (e < EE) atomicAdd(&g_counts[ei[EE + e]], 1);
}

__device__ void body_a(int vb, const float* mean, const float* cov) {
    int warp = threadIdx.x >> 5, lane = threadIdx.x & 31;
    int n = vb * 8 + warp;
    if (n >= NN) return;
    const float* x = cov + (size_t)n * 256;
    float4 as = make_float4(0, 0, 0, 0), ad = make_float4(0, 0, 0, 0);
    for (int r = lane; r < 256; r += 32) {
        float xv = __ldg(x + r);
        float4 ws = g_wsrc_cov[r], wd = g_wdst_cov[r];
        as.x += xv * ws.x; as.y += xv * ws.y; as.z += xv * ws.z; as.w += xv * ws.w;
        ad.x += xv * wd.x; ad.y += xv * wd.y; ad.z += xv * wd.z; ad.w += xv * wd.w;
    }
    wred_sum4(as); wred_sum4(ad);
    float4 ms = make_float4(0, 0, 0, 0), md = make_float4(0, 0, 0, 0);
    if (lane < 16) {
        float xv = __ldg(mean + (size_t)n * 16 + lane);
        float4 ws = g_wsrc_mean[lane], wd = g_wdst_mean[lane];
        ms = make_float4(xv * ws.x, xv * ws.y, xv * ws.z, xv * ws.w);
        md = make_float4(xv * wd.x, xv * wd.y, xv * wd.z, xv * wd.w);
    }
    wred_sum4(ms); wred_sum4(md);
    if (lane == 0) {
        g_srcA[2 * n]     = as;
        g_srcA[2 * n + 1] = ms;
        g_dstA[2 * n]     = ad;
        g_dstA[2 * n + 1] = md;
    }
}

__device__ void body_gemm_mean(int vb, const float* X) {
    __shared__ float xs[16][16];
    __shared__ float ws[16][64];
    int t = threadIdx.x;
    int row0 = vb * 16;
    xs[t >> 4][t & 15] = X[(size_t)row0 * 16 + t];
    for (int i = t; i < 1024; i += 256) ws[i >> 6][i & 63] = g_Wfold_mean[i];
    __syncthreads();
    int r = t >> 4, cg = (t & 15) << 2;
    float4 acc = make_float4(0, 0, 0, 0);
#pragma unroll
    for (int k = 0; k < 16; k++) {
        float a = xs[r][k];
        acc.x += a * ws[k][cg + 0];
        acc.y += a * ws[k][cg + 1];
        acc.z += a * ws[k][cg + 2];
        acc.w += a * ws[k][cg + 3];
    }
    *(float4*)(g_xh_mean + (size_t)(row0 + r) * 64 + cg) = acc;
}

// ================= combo kernels =================

__global__ void __launch_bounds__(256) k_combo1(
    const float* __restrict__ fcv_W1, const float* __restrict__ fcv_W2,
    const float* __restrict__ W_cov, const float* __restrict__ att_src_c,
    const float* __restrict__ att_dst_c,
    const float* __restrict__ fm_W1, const float* __restrict__ fm_W2,
    const float* __restrict__ fm_b1, const float* __restrict__ fm_b2,
    const float* __restrict__ bias_mean, const float* __restrict__ W_mean,
    const float* __restrict__ att_src_m, const float* __restrict__ att_dst_m) {
    int b = blockIdx.x;
    if (b < 256)       body_Wc2(b, fcv_W1, fcv_W2);
    else if (b < 452)  body_init_counts(b - 256);
    else if (b < 460)  body_att_cov(b - 452, W_cov, att_src_c, att_dst_c);
    else               body_prep_mean(fm_W1, fm_W2, fm_b1, fm_b2, bias_mean,
                                      W_mean, att_src_m, att_dst_m);
}

__global__ void __launch_bounds__(256) k_combo2(
    const float* __restrict__ mean, const float* __restrict__ cov,
    const int* __restrict__ ei, const float* __restrict__ W_cov,
    const float* __restrict__ bias_cov, const float* __restrict__ fcv_b1,
    const float* __restrict__ fcv_W2, const float* __restrict__ fcv_b2) {
    int b = blockIdx.x;
    if (b < 6250)        body_a(b, mean, cov);
    else if (b < 9375)   body_hist(b - 6250, ei);
    else if (b < 12500)  body_gemm_mean(b - 9375, mean);
    else if (b < 12756)  body_Wfold_cov(b - 12500, W_cov);
    else                 body_bias_cov(bias_cov, fcv_b1, fcv_W2, fcv_b2);
}

// ---------------- scan ----------------
__global__ void k_scan() {
    __shared__ int ssum[1024];
    int t = threadIdx.x;
    const int PER = (NN + 1023) / 1024;
    int base = t * PER;
    int local = 0;
    for (int i = 0; i < PER; i++) { int idx = base + i; if (idx < NN) local += g_counts[idx]; }
    ssum[t] = local;
    __syncthreads();
    for (int off = 1; off < 1024; off <<= 1) {
        int v = (t >= off) ? ssum[t - off] : 0;
        __syncthreads();
        ssum[t] += v;
        __syncthreads();
    }
    int prefix = (t == 0) ? 0 : ssum[t - 1];
    for (int i = 0; i < PER; i++) {
        int idx = base + i;
        if (idx < NN) {
            g_offsets[idx] = prefix;
            g_cursor[idx] = prefix;
            prefix += g_counts[idx];
        }
    }
    if (t == 1023) g_offsets[NN] = ssum[1023];
}

// scatter: CSR ids + per-edge exp numerators (interleaved cov/mean pairs)
__global__ void k_scatter(const int* __restrict__ ei) {
    int e = blockIdx.x * 256 + threadIdx.x;
    if (e >= ETOT) return;
    int s, d;
    if (e < EE) { s = ei[e]; d = ei[EE + e]; }
    else        { s = e - EE; d = s; }
    int pos = atomicAdd(&g_cursor[d], 1);
    g_csr_src[pos] = s;
    float4 ac = g_srcA[2 * s], am = g_srcA[2 * s + 1];
    float4 dc = g_dstA[2 * d], dm = g_dstA[2 * d + 1];
    g_coef[2 * (size_t)pos] =
        make_float4(__expf(lrelu(ac.x + dc.x)), __expf(lrelu(ac.y + dc.y)),
                    __expf(lrelu(ac.z + dc.z)), __expf(lrelu(ac.w + dc.w)));
    g_coef[2 * (size_t)pos + 1] =
        make_float4(__expf(lrelu(am.x + dm.x)), __expf(lrelu(am.y + dm.y)),
                    __expf(lrelu(am.z + dm.z)), __expf(lrelu(am.w + dm.w)));
}

// ---------------- fused aggregation (no stats pass: raw-numerator accumulation,
// denominators accumulated during staging, single end-of-block reduce + scale) ------------
__global__ void __launch_bounds__(320) k_agg_fused(const float* __restrict__ cov,
                                                   float* __restrict__ out_mean) {
    __shared__ float4 cfs[256];
    __shared__ float4 cfm[256];
    __shared__ int    srcs[256];
    __shared__ float4 redc[8], redm[8];
    __shared__ float  mred[64];
    int dst = blockIdx.x;
    int t = threadIdx.x;
    int warp = t >> 5, lane = t & 31;
    int beg = g_offsets[dst];
    int deg = g_offsets[dst + 1] - beg;

    float a0 = 0.f, a1 = 0.f, a2 = 0.f, a3 = 0.f;   // raw cov accum (t<256)
    float accm = 0.f;                                // raw mean accum (t>=256)
    float4 dpc = make_float4(0, 0, 0, 0);            // denominator partials (stagers only)
    float4 dpm = make_float4(0, 0, 0, 0);
    int mh = (t - 256) >> 4, mc = (t - 256) & 15;

    for (int c0 = 0; c0 < deg; c0 += 256) {
        int cnt = min(256, deg - c0);
        if (t < cnt) {
            size_t idx = (size_t)(beg + c0 + t);
            srcs[t] = g_csr_src[idx];
            float4 c = g_coef[2 * idx];
            float4 m = g_coef[2 * idx + 1];
            cfs[t] = c; cfm[t] = m;
            dpc.x += c.x; dpc.y += c.y; dpc.z += c.z; dpc.w += c.w;
            dpm.x += m.x; dpm.y += m.y; dpm.z += m.z; dpm.w += m.w;
        }
        __syncthreads();
        if (t < 256) {
#pragma unroll 4
            for (int j = 0; j < cnt; j++) {
                float4 cf = cfs[j];
                float v = __ldg(cov + (size_t)srcs[j] * 256 + t);
                a0 += cf.x * v; a1 += cf.y * v; a2 += cf.z * v; a3 += cf.w * v;
            }
        } else {
#pragma unroll 4
            for (int j = 0; j < cnt; j++) {
                const float* cf = (const float*)&cfm[j];
                accm += cf[mh] * __ldg(g_xh_mean + (size_t)srcs[j] * 64 + mh * 16 + mc);
            }
        }
        __syncthreads();
    }

    // block-reduce denominators (warps 8,9 contributed zero and don't write)
    wred_sum4(dpc);
    wred_sum4(dpm);
    if (lane == 0 && warp < 8) { redc[warp] = dpc; redm[warp] = dpm; }
    __syncthreads();
    float4 sc = redc[0], smm = redm[0];
#pragma unroll
    for (int i = 1; i < 8; i++) {
        float4 c = redc[i], m = redm[i];
        sc.x += c.x; sc.y += c.y; sc.z += c.z; sc.w += c.w;
        smm.x += m.x; smm.y += m.y; smm.z += m.z; smm.w += m.w;
    }

    if (t < 256) {
        float* zp = g_z + (size_t)dst * 1024 + t;
        zp[0]   = to_tf32(a0 / (sc.x + 1e-16f));
        zp[256] = to_tf32(a1 / (sc.y + 1e-16f));
        zp[512] = to_tf32(a2 / (sc.z + 1e-16f));
        zp[768] = to_tf32(a3 / (sc.w + 1e-16f));
    } else {
        float invm = 1.f / (((const float*)&smm)[mh] + 1e-16f);
        mred[t - 256] = accm * invm;
    }
    __syncthreads();
    if (t < 16)
        out_mean[(size_t)dst * 16 + t] =
            0.25f * (mred[t] + mred[16 + t] + mred[32 + t] + mred[48 + t])
            + g_bias_mean_out[t];
}

// ---------------- tf32 mma.sync GEMM (R3-proven: BM=BN=128, 2 CTAs/SM) ----------------
#define SG_STRIDE 36
#define SG_BUFSZ  (128 * SG_STRIDE)
#define SG_SMEM_FLOATS (SG_BUFSZ * 4)
__global__ void __launch_bounds__(256) k_mma_cov(float* __restrict__ out) {
    extern __shared__ float smf[];
    uint32_t sbase = smem_u32(smf);
    int t = threadIdx.x, wid = t >> 5, lane = t & 31;
    int tq = lane >> 2, tr = lane & 3;
    int bm = blockIdx.y * 128;
    int bn = blockIdx.x * 128;
    int wm = (wid >> 2) * 64;
    int wn = (wid & 3) * 32;

    float acc[4][4][4];
#pragma unroll
    for (int mi = 0; mi < 4; mi++)
#pragma unroll
        for (int ni = 0; ni < 4; ni++)
#pragma unroll
            for (int q = 0; q < 4; q++) acc[mi][ni][q] = 0.f;

    auto stage = [&](int c, int buf) {
        int kc = c * 32;
        uint32_t aoff = sbase + (uint32_t)(buf * SG_BUFSZ) * 4;
        uint32_t boff = sbase + (uint32_t)((2 + buf) * SG_BUFSZ) * 4;
#pragma unroll
        for (int i = 0; i < 4; i++) {
            int f = i * 256 + t;
            int r = f >> 3, q = f & 7;
            const float* src = g_z + (size_t)(bm + r) * 1024 + kc + q * 4;  // NPAD-padded: no guard
            cp16(aoff + (uint32_t)(r * SG_STRIDE + q * 4) * 4, src);
        }
#pragma unroll
        for (int i = 0; i < 4; i++) {
            int f = i * 256 + t;
            int r = f >> 3, q = f & 7;
            const float* src = g_BT + (size_t)(bn + r) * 1024 + kc + q * 4;
            cp16(boff + (uint32_t)(r * SG_STRIDE + q * 4) * 4, src);
        }
        CP_COMMIT();
    };

    stage(0, 0);
    for (int c = 0; c < 32; c++) {
        int buf = c & 1;
        if (c < 31) {
            stage(c + 1, (c + 1) & 1);
            asm volatile("cp.async.wait_group 1;" ::: "memory");
        } else {
            asm volatile("cp.async.wait_group 0;" ::: "memory");
        }
        __syncthreads();
        const float* As = smf + buf * SG_BUFSZ;
        const float* Bs = smf + (2 + buf) * SG_BUFSZ;
#pragma unroll
        for (int kk = 0; kk < 4; kk++) {
            int k8 = kk * 8;
            uint32_t af[4][4], bf[4][2];
#pragma unroll
            for (int mi = 0; mi < 4; mi++) {
                const float* ap = As + (wm + mi * 16 + tq) * SG_STRIDE + k8 + tr;
                af[mi][0] = __float_as_uint(ap[0]);
                af[mi][1] = __float_as_uint(ap[8 * SG_STRIDE]);
                af[mi][2] = __float_as_uint(ap[4]);
                af[mi][3] = __float_as_uint(ap[8 * SG_STRIDE + 4]);
            }
#pragma unroll
            for (int ni = 0; ni < 4; ni++) {
                const float* bp = Bs + (wn + ni * 8 + tq) * SG_STRIDE + k8 + tr;
                bf[ni][0] = __float_as_uint(bp[0]);
                bf[ni][1] = __float_as_uint(bp[4]);
            }
#pragma unroll
            for (int mi = 0; mi < 4; mi++)
#pragma unroll
                for (int ni = 0; ni < 4; ni++)
                    MMA_TF32(acc[mi][ni], af[mi], bf[ni]);
        }
        __syncthreads();
    }

#pragma unroll
    for (int mi = 0; mi < 4; mi++) {
#pragma unroll
        for (int ni = 0; ni < 4; ni++) {
            int cc = bn + wn + ni * 8 + 2 * tr;
            float b0 = g_bias_cov_out[cc], b1 = g_bias_cov_out[cc + 1];
            int r0 = bm + wm + mi * 16 + tq;
            if (r0 < NN) {
                float2 v = make_float2(acc[mi][ni][0] + b0, acc[mi][ni][1] + b1);
                *(float2*)(out + (size_t)r0 * 256 + cc) = v;
            }
            int r1 = r0 + 8;
            if (r1 < NN) {
                float2 v = make_float2(acc[mi][ni][2] + b0, acc[mi][ni][3] + b1);
                *(float2*)(out + (size_t)r1 * 256 + cc) = v;
            }
        }
    }
}

// ---------------- launch ----------------
extern "C" void kernel_launch(void* const* d_in, const int* in_sizes, int n_in,
                              void* d_out, int out_size) {
    const float* mean        = (const float*)d_in[0];
    const float* cov         = (const float*)d_in[1];
    const int*   edge_index  = (const int*)  d_in[2];
    const float* W_mean      = (const float*)d_in[3];
    const float* att_src_m   = (const float*)d_in[4];
    const float* att_dst_m   = (const float*)d_in[5];
    const float* bias_mean   = (const float*)d_in[6];
    const float* W_cov       = (const float*)d_in[7];
    const float* att_src_c   = (const float*)d_in[8];
    const float* att_dst_c   = (const float*)d_in[9];
    const float* bias_cov    = (const float*)d_in[10];
    const float* fm_W1       = (const float*)d_in[11];
    const float* fm_b1       = (const float*)d_in[12];
    const float* fm_W2       = (const float*)d_in[13];
    const float* fm_b2       = (const float*)d_in[14];
    const float* fcv_W1      = (const float*)d_in[15];
    const float* fcv_b1      = (const float*)d_in[16];
    const float* fcv_W2      = (const float*)d_in[17];
    const float* fcv_b2      = (const float*)d_in[18];
    float* outp = (float*)d_out;

    cudaFuncSetAttribute(k_mma_cov, cudaFuncAttributeMaxDynamicSharedMemorySize,
                         SG_SMEM_FLOATS * 4);

    // phase 1: input-only work
    k_combo1<<<461, 256>>>(fcv_W1, fcv_W2, W_cov, att_src_c, att_dst_c,
                           fm_W1, fm_W2, fm_b1, fm_b2, bias_mean, W_mean,
                           att_src_m, att_dst_m);

    // phase 2: logits, hist, mean proj, Wfold, bias
    k_combo2<<<12757, 256>>>(mean, cov, edge_index, W_cov,
                             bias_cov, fcv_b1, fcv_W2, fcv_b2);

    // phase 3-4: CSR finalize; scatter emits interleaved per-edge exp numerators
    k_scan<<<1, 1024>>>();
    k_scatter<<<(ETOT + 255) / 256, 256>>>(edge_index);

    // phase 5: fused aggregation (raw-numerator accumulation, end-of-block normalize)
    k_agg_fused<<<NN, 320>>>(cov, outp);

    // phase 6: tensor-core projection of z
    dim3 gg(2, (NN + 127) / 128);
    k_mma_cov<<<gg, 256, SG_SMEM_FLOATS * 4>>>(outp + (size_t)NN * 16);
}

// round 12
// speedup vs baseline: 1.2233x; 1.2233x over previous
#include <cuda_runtime.h>
#include <cstdint>

#define NN 50000
#define NPAD 50048
#define EE 800000
#define ETOT (EE + NN)

// ---------------- scratch ----------------
__device__ float  g_z[(size_t)NPAD * 1024];   // rows >= NN never written; .bss zero-init
__device__ float  g_xh_mean[(size_t)NN * 64];
__device__ float4 g_srcA[NN * 2];   // [2n]=cov logits (src), [2n+1]=mean logits (src)
__device__ float4 g_dstA[NN * 2];
__device__ float  g_Wc2[256 * 256];
__device__ float  g_BT[256 * 1024];
__device__ float  g_Wfold_mean[16 * 64];
__device__ float4 g_wsrc_cov[256], g_wdst_cov[256];
__device__ float4 g_wsrc_mean[16], g_wdst_mean[16];
__device__ float  g_bias_cov_out[256];
__device__ float  g_bias_mean_out[16];
__device__ int    g_counts[NN];
__device__ int    g_offsets[NN + 1];
__device__ int    g_cursor[NN];
__device__ int    g_csr_src[ETOT];
__device__ float4 g_coefC[ETOT];    // exp numerators (cov), per edge, CSR order
__device__ float4 g_coefM[ETOT];    // exp numerators (mean)

__device__ __forceinline__ float lrelu(float x) { return x > 0.f ? x : 0.2f * x; }

__device__ __forceinline__ float to_tf32(float x) {
    float r;
    asm("cvt.rna.tf32.f32 %0, %1;" : "=f"(r) : "f"(x));
    return r;
}

__device__ __forceinline__ void wred_sum4(float4& v) {
#pragma unroll
    for (int o = 16; o; o >>= 1) {
        v.x += __shfl_xor_sync(0xffffffffu, v.x, o);
        v.y += __shfl_xor_sync(0xffffffffu, v.y, o);
        v.z += __shfl_xor_sync(0xffffffffu, v.z, o);
        v.w += __shfl_xor_sync(0xffffffffu, v.w, o);
    }
}

// ---------------- cp.async / mma helpers ----------------
__device__ __forceinline__ uint32_t smem_u32(const void* p) {
    uint32_t a;
    asm("{ .reg .u64 tmp; cvta.to.shared.u64 tmp, %1; cvt.u32.u64 %0, tmp; }" : "=r"(a) : "l"(p));
    return a;
}
__device__ __forceinline__ void cp16(uint32_t dst, const void* src) {
    asm volatile("cp.async.cg.shared.global [%0], [%1], 16;" :: "r"(dst), "l"(src));
}
#define CP_COMMIT() asm volatile("cp.async.commit_group;" ::: "memory")

#define MMA_TF32(d, a, b) \
    asm volatile("mma.sync.aligned.m16n8k8.row.col.f32.tf32.tf32.f32 " \
        "{%0,%1,%2,%3}, {%4,%5,%6,%7}, {%8,%9}, {%0,%1,%2,%3};" \
        : "+f"((d)[0]), "+f"((d)[1]), "+f"((d)[2]), "+f"((d)[3]) \
        : "r"((a)[0]), "r"((a)[1]), "r"((a)[2]), "r"((a)[3]), "r"((b)[0]), "r"((b)[1]))

// ================= device-side phase bodies =================

__device__ void body_prep_mean(const float* fmW1, const float* fmW2,
                               const float* fmb1, const float* fmb2,
                               const float* bias_mean, const float* W_mean,
                               const float* att_src, const float* att_dst) {
    __shared__ float Wm2s[16][16];
    int t = threadIdx.x;
    {
        int r = t >> 4, c = t & 15;
        float s = 0.f;
        for (int k = 0; k < 16; k++) s += fmW1[r * 16 + k] * fmW2[k * 16 + c];
        Wm2s[r][c] = s;
    }
    if (t < 128) {
        int sd = t >> 6, rem = t & 63, r = rem >> 2, h = rem & 3;
        const float* att = sd ? att_dst : att_src;
        float s = 0.f;
        for (int j = 0; j < 16; j++) s += W_mean[r * 64 + h * 16 + j] * att[h * 16 + j];
        float* dstp = sd ? (float*)g_wdst_mean : (float*)g_wsrc_mean;
        dstp[r * 4 + h] = s;
    }
    __syncthreads();
    if (t < 16) {
        float b = fmb2[t];
        for (int k = 0; k < 16; k++)
            b += bias_mean[k] * Wm2s[k][t] + fmb1[k] * fmW2[k * 16 + t];
        g_bias_mean_out[t] = b;
    }
    for (int o = t; o < 1024; o += 256) {
        int r = o >> 6, hc = o & 63, h = hc >> 4, c = hc & 15;
        float s = 0.f;
        for (int j = 0; j < 16; j++) s += W_mean[r * 64 + h * 16 + j] * Wm2s[j][c];
        g_Wfold_mean[o] = s;
    }
}

__device__ void body_Wc2(int vb, const float* W1, const float* W2) {
    int r = vb, c = threadIdx.x;
    float s = 0.f;
    for (int k = 0; k < 256; k++) s += W1[r * 256 + k] * W2[k * 256 + c];
    g_Wc2[r * 256 + c] = s;
}

__device__ void body_att_cov(int vb, const float* W_cov, const float* att_src,
                             const float* att_dst) {
    int o = vb * 256 + threadIdx.x;
    int sd = o >> 10, rem = o & 1023, r = rem >> 2, h = rem & 3;
    const float* att = sd ? att_dst : att_src;
    const float* wrow = W_cov + (size_t)r * 1024 + h * 256;
    float s = 0.f;
    for (int j = 0; j < 256; j++) s += wrow[j] * att[h * 256 + j];
    float* dstp = sd ? (float*)g_wdst_cov : (float*)g_wsrc_cov;
    dstp[r * 4 + h] = s;
}

__device__ void body_init_counts(int vb) {
    int i = vb * 256 + threadIdx.x;
    if (i < NN) g_counts[i] = 1;
}

__device__ void body_bias_cov(const float* bias_cov, const float* fb1,
                              const float* fW2, const float* fb2) {
    int c = threadIdx.x;
    float b = fb2[c];
    for (int k = 0; k < 256; k++)
        b += bias_cov[k] * g_Wc2[k * 256 + c] + fb1[k] * fW2[k * 256 + c];
    g_bias_cov_out[c] = b;
}

__device__ void body_Wfold_cov(int vb, const float* W_cov) {
    __shared__ float wc2s[32][256];
    __shared__ float wr[4][256];
    int seg = vb & 3, r0 = (vb >> 2) * 4;
    int t = threadIdx.x;
    float acc[4];
#pragma unroll
    for (int i = 0; i < 4; i++) acc[i] = 0.f;
#pragma unroll
    for (int i = 0; i < 4; i++)
        wr[i][t] = W_cov[(size_t)(r0 + i) * 1024 + seg * 256 + t];
    __syncthreads();
    for (int j0 = 0; j0 < 256; j0 += 32) {
        for (int i = 0; i < 32; i++)
            wc2s[i][t] = g_Wc2[(size_t)(j0 + i) * 256 + t];
        __syncthreads();
#pragma unroll
        for (int jj = 0; jj < 32; jj++) {
            float b = wc2s[jj][t];
#pragma unroll
            for (int i = 0; i < 4; i++) acc[i] += wr[i][j0 + jj] * b;
        }
        __syncthreads();
    }
#pragma unroll
    for (int i = 0; i < 4; i++)
        g_BT[(size_t)t * 1024 + seg * 256 + r0 + i] = to_tf32(0.25f * acc[i]);
}

__device__ void body_hist(int vb, const int* ei) {
    int e = vb * 256 + threadIdx.x;
    if (e < EE) atomicAdd(&g_counts[ei[EE + e]], 1);
}

__device__ void body_a(int vb, const float* mean, const float* cov) {
    int warp = threadIdx.x >> 5, lane = threadIdx.x & 31;
    int n = vb * 8 + warp;
    if (n >= NN) return;
    const float* x = cov + (size_t)n * 256;
    float4 as = make_float4(0, 0, 0, 0), ad = make_float4(0, 0, 0, 0);
    for (int r = lane; r < 256; r += 32) {
        float xv = __ldg(x + r);
        float4 ws = g_wsrc_cov[r], wd = g_wdst_cov[r];
        as.x += xv * ws.x; as.y += xv * ws.y; as.z += xv * ws.z; as.w += xv * ws.w;
        ad.x += xv * wd.x; ad.y += xv * wd.y; ad.z += xv * wd.z; ad.w += xv * wd.w;
    }
    wred_sum4(as); wred_sum4(ad);
    float4 ms = make_float4(0, 0, 0, 0), md = make_float4(0, 0, 0, 0);
    if (lane < 16) {
        float xv = __ldg(mean + (size_t)n * 16 + lane);
        float4 ws = g_wsrc_mean[lane], wd = g_wdst_mean[lane];
        ms = make_float4(xv * ws.x, xv * ws.y, xv * ws.z, xv * ws.w);
        md = make_float4(xv * wd.x, xv * wd.y, xv * wd.z, xv * wd.w);
    }
    wred_sum4(ms); wred_sum4(md);
    if (lane == 0) {
        g_srcA[2 * n]     = as;
        g_srcA[2 * n + 1] = ms;
        g_dstA[2 * n]     = ad;
        g_dstA[2 * n + 1] = md;
    }
}

__device__ void body_gemm_mean(int vb, const float* X) {
    __shared__ float xs[16][16];
    __shared__ float ws[16][64];
    int t = threadIdx.x;
    int row0 = vb * 16;
    xs[t >> 4][t & 15] = X[(size_t)row0 * 16 + t];
    for (int i = t; i < 1024; i += 256) ws[i >> 6][i & 63] = g_Wfold_mean[i];
    __syncthreads();
    int r = t >> 4, cg = (t & 15) << 2;
    float4 acc = make_float4(0, 0, 0, 0);
#pragma unroll
    for (int k = 0; k < 16; k++) {
        float a = xs[r][k];
        acc.x += a * ws[k][cg + 0];
        acc.y += a * ws[k][cg + 1];
        acc.z += a * ws[k][cg + 2];
        acc.w += a * ws[k][cg + 3];
    }
    *(float4*)(g_xh_mean + (size_t)(row0 + r) * 64 + cg) = acc;
}

// ================= combo kernels =================

__global__ void __launch_bounds__(256) k_combo1(
    const float* __restrict__ fcv_W1, const float* __restrict__ fcv_W2,
    const float* __restrict__ W_cov, const float* __restrict__ att_src_c,
    const float* __restrict__ att_dst_c,
    const float* __restrict__ fm_W1, const float* __restrict__ fm_W2,
    const float* __restrict__ fm_b1, const float* __restrict__ fm_b2,
    const float* __restrict__ bias_mean, const float* __restrict__ W_mean,
    const float* __restrict__ att_src_m, const float* __restrict__ att_dst_m) {
    int b = blockIdx.x;
    if (b < 256)       body_Wc2(b, fcv_W1, fcv_W2);
    else if (b < 452)  body_init_counts(b - 256);
    else if (b < 460)  body_att_cov(b - 452, W_cov, att_src_c, att_dst_c);
    else               body_prep_mean(fm_W1, fm_W2, fm_b1, fm_b2, bias_mean,
                                      W_mean, att_src_m, att_dst_m);
}

__global__ void __launch_bounds__(256) k_combo2(
    const float* __restrict__ mean, const float* __restrict__ cov,
    const int* __restrict__ ei, const float* __restrict__ W_cov,
    const float* __restrict__ bias_cov, const float* __restrict__ fcv_b1,
    const float* __restrict__ fcv_W2, const float* __restrict__ fcv_b2) {
    int b = blockIdx.x;
    if (b < 6250)        body_a(b, mean, cov);
    else if (b < 9375)   body_hist(b - 6250, ei);
    else if (b < 12500)  body_gemm_mean(b - 9375, mean);
    else if (b < 12756)  body_Wfold_cov(b - 12500, W_cov);
    else                 body_bias_cov(bias_cov, fcv_b1, fcv_W2, fcv_b2);
}

// ---------------- scan ----------------
__global__ void k_scan() {
    __shared__ int ssum[1024];
    int t = threadIdx.x;
    const int PER = (NN + 1023) / 1024;
    int base = t * PER;
    int local = 0;
    for (int i = 0; i < PER; i++) { int idx = base + i; if (idx < NN) local += g_counts[idx]; }
    ssum[t] = local;
    __syncthreads();
    for (int off = 1; off < 1024; off <<= 1) {
        int v = (t >= off) ? ssum[t - off] : 0;
        __syncthreads();
        ssum[t] += v;
        __syncthreads();
    }
    int prefix = (t == 0) ? 0 : ssum[t - 1];
    for (int i = 0; i < PER; i++) {
        int idx = base + i;
        if (idx < NN) {
            g_offsets[idx] = prefix;
            g_cursor[idx] = prefix;
            prefix += g_counts[idx];
        }
    }
    if (t == 1023) g_offsets[NN] = ssum[1023];
}

// scatter: build CSR ids AND per-edge exp numerators (random node-table reads done ONCE here)
__global__ void k_scatter(const int* __restrict__ ei) {
    int e = blockIdx.x * 256 + threadIdx.x;
    if (e >= ETOT) return;
    int s, d;
    if (e < EE) { s = ei[e]; d = ei[EE + e]; }
    else        { s = e - EE; d = s; }
    int pos = atomicAdd(&g_cursor[d], 1);
    g_csr_src[pos] = s;
    float4 ac = g_srcA[2 * s], dc = g_dstA[2 * d];
    g_coefC[pos] = make_float4(__expf(lrelu(ac.x + dc.x)), __expf(lrelu(ac.y + dc.y)),
                               __expf(lrelu(ac.z + dc.z)), __expf(lrelu(ac.w + dc.w)));
    float4 am = g_srcA[2 * s + 1], dm = g_dstA[2 * d + 1];
    g_coefM[pos] = make_float4(__expf(lrelu(am.x + dm.x)), __expf(lrelu(am.y + dm.y)),
                               __expf(lrelu(am.z + dm.z)), __expf(lrelu(am.w + dm.w)));
}

// ---------------- fused aggregation (R9-proven: streaming stats pass + streaming coefs) ----
__global__ void __launch_bounds__(320) k_agg_fused(const float* __restrict__ cov,
                                                   float* __restrict__ out_mean) {
    __shared__ float4 cfs[256];
    __shared__ float4 cfm[256];
    __shared__ int    srcs[256];
    __shared__ float4 s_invc, s_invm;
    __shared__ float  mred[64];
    int dst = blockIdx.x;
    int t = threadIdx.x;
    int warp = t >> 5, lane = t & 31;
    int beg = g_offsets[dst];
    int deg = g_offsets[dst + 1] - beg;

    if (warp == 0) {          // cov denominators: streaming sum of numerators
        float4 sc = make_float4(0, 0, 0, 0);
        for (int j = lane; j < deg; j += 32) {
            float4 c = g_coefC[beg + j];
            sc.x += c.x; sc.y += c.y; sc.z += c.z; sc.w += c.w;
        }
        wred_sum4(sc);
        if (lane == 0)
            s_invc = make_float4(1.f / (sc.x + 1e-16f), 1.f / (sc.y + 1e-16f),
                                 1.f / (sc.z + 1e-16f), 1.f / (sc.w + 1e-16f));
    } else if (warp == 8) {   // mean denominators
        float4 sm = make_float4(0, 0, 0, 0);
        for (int j = lane; j < deg; j += 32) {
            float4 c = g_coefM[beg + j];
            sm.x += c.x; sm.y += c.y; sm.z += c.z; sm.w += c.w;
        }
        wred_sum4(sm);
        if (lane == 0)
            s_invm = make_float4(1.f / (sm.x + 1e-16f), 1.f / (sm.y + 1e-16f),
                                 1.f / (sm.z + 1e-16f), 1.f / (sm.w + 1e-16f));
    }
    __syncthreads();

    float a0 = 0.f, a1 = 0.f, a2 = 0.f, a3 = 0.f;
    float accm = 0.f;
    int mh = (t - 256) >> 4, mc = (t - 256) & 15;

    for (int c0 = 0; c0 < deg; c0 += 256) {
        int cnt = min(256, deg - c0);
        if (t < cnt) {
            srcs[t] = g_csr_src[beg + c0 + t];
            float4 c = g_coefC[beg + c0 + t];
            cfs[t] = make_float4(c.x * s_invc.x, c.y * s_invc.y,
                                 c.z * s_invc.z, c.w * s_invc.w);
            float4 m = g_coefM[beg + c0 + t];
            cfm[t] = make_float4(m.x * s_invm.x, m.y * s_invm.y,
                                 m.z * s_invm.z, m.w * s_invm.w);
        }
        __syncthreads();
        if (t < 256) {
#pragma unroll 4
            for (int j = 0; j < cnt; j++) {
                float4 cf = cfs[j];
                float v = __ldg(cov + (size_t)srcs[j] * 256 + t);
                a0 += cf.x * v; a1 += cf.y * v; a2 += cf.z * v; a3 += cf.w * v;
            }
        } else {
#pragma unroll 4
            for (int j = 0; j < cnt; j++) {
                const float* cf = (const float*)&cfm[j];
                accm += cf[mh] * __ldg(g_xh_mean + (size_t)srcs[j] * 64 + mh * 16 + mc);
            }
        }
        __syncthreads();
    }

    if (t < 256) {
        float* zp = g_z + (size_t)dst * 1024 + t;
        zp[0]   = to_tf32(a0);
        zp[256] = to_tf32(a1);
        zp[512] = to_tf32(a2);
        zp[768] = to_tf32(a3);
    } else {
        mred[t - 256] = accm;
    }
    __syncthreads();
    if (t < 16)
        out_mean[(size_t)dst * 16 + t] =
            0.25f * (mred[t] + mred[16 + t] + mred[32 + t] + mred[48 + t])
            + g_bias_mean_out[t];
}

// ---------------- tf32 mma.sync GEMM (R3-proven: BM=BN=128, 2 CTAs/SM; NPAD unguarded A) ---
#define SG_STRIDE 36
#define SG_BUFSZ  (128 * SG_STRIDE)
#define SG_SMEM_FLOATS (SG_BUFSZ * 4)
__global__ void __launch_bounds__(256) k_mma_cov(float* __restrict__ out) {
    extern __shared__ float smf[];
    uint32_t sbase = smem_u32(smf);
    int t = threadIdx.x, wid = t >> 5, lane = t & 31;
    int tq = lane >> 2, tr = lane & 3;
    int bm = blockIdx.y * 128;
    int bn = blockIdx.x * 128;
    int wm = (wid >> 2) * 64;
    int wn = (wid & 3) * 32;

    float acc[4][4][4];
#pragma unroll
    for (int mi = 0; mi < 4; mi++)
#pragma unroll
        for (int ni = 0; ni < 4; ni++)
#pragma unroll
            for (int q = 0; q < 4; q++) acc[mi][ni][q] = 0.f;

    auto stage = [&](int c, int buf) {
        int kc = c * 32;
        uint32_t aoff = sbase + (uint32_t)(buf * SG_BUFSZ) * 4;
        uint32_t boff = sbase + (uint32_t)((2 + buf) * SG_BUFSZ) * 4;
#pragma unroll
        for (int i = 0; i < 4; i++) {
            int f = i * 256 + t;
            int r = f >> 3, q = f & 7;
            const float* src = g_z + (size_t)(bm + r) * 1024 + kc + q * 4;  // NPAD: no guard
            cp16(aoff + (uint32_t)(r * SG_STRIDE + q * 4) * 4, src);
        }
#pragma unroll
        for (int i = 0; i < 4; i++) {
            int f = i * 256 + t;
            int r = f >> 3, q = f & 7;
            const float* src = g_BT + (size_t)(bn + r) * 1024 + kc + q * 4;
            cp16(boff + (uint32_t)(r * SG_STRIDE + q * 4) * 4, src);
        }
        CP_COMMIT();
    };

    stage(0, 0);
    for (int c = 0; c < 32; c++) {
        int buf = c & 1;
        if (c < 31) {
            stage(c + 1, (c + 1) & 1);
            asm volatile("cp.async.wait_group 1;" ::: "memory");
        } else {
            asm volatile("cp.async.wait_group 0;" ::: "memory");
        }
        __syncthreads();
        const float* As = smf + buf * SG_BUFSZ;
        const float* Bs = smf + (2 + buf) * SG_BUFSZ;
#pragma unroll
        for (int kk = 0; kk < 4; kk++) {
            int k8 = kk * 8;
            uint32_t af[4][4], bf[4][2];
#pragma unroll
            for (int mi = 0; mi < 4; mi++) {
                const float* ap = As + (wm + mi * 16 + tq) * SG_STRIDE + k8 + tr;
                af[mi][0] = __float_as_uint(ap[0]);
                af[mi][1] = __float_as_uint(ap[8 * SG_STRIDE]);
                af[mi][2] = __float_as_uint(ap[4]);
                af[mi][3] = __float_as_uint(ap[8 * SG_STRIDE + 4]);
            }
#pragma unroll
            for (int ni = 0; ni < 4; ni++) {
                const float* bp = Bs + (wn + ni * 8 + tq) * SG_STRIDE + k8 + tr;
                bf[ni][0] = __float_as_uint(bp[0]);
                bf[ni][1] = __float_as_uint(bp[4]);
            }
#pragma unroll
            for (int mi = 0; mi < 4; mi++)
#pragma unroll
                for (int ni = 0; ni < 4; ni++)
                    MMA_TF32(acc[mi][ni], af[mi], bf[ni]);
        }
        __syncthreads();
    }

#pragma unroll
    for (int mi = 0; mi < 4; mi++) {
#pragma unroll
        for (int ni = 0; ni < 4; ni++) {
            int cc = bn + wn + ni * 8 + 2 * tr;
            float b0 = g_bias_cov_out[cc], b1 = g_bias_cov_out[cc + 1];
            int r0 = bm + wm + mi * 16 + tq;
            if (r0 < NN) {
                float2 v = make_float2(acc[mi][ni][0] + b0, acc[mi][ni][1] + b1);
                *(float2*)(out + (size_t)r0 * 256 + cc) = v;
            }
            int r1 = r0 + 8;
            if (r1 < NN) {
                float2 v = make_float2(acc[mi][ni][2] + b0, acc[mi][ni][3] + b1);
                *(float2*)(out + (size_t)r1 * 256 + cc) = v;
            }
        }
    }
}

// ---------------- launch ----------------
extern "C" void kernel_launch(void* const* d_in, const int* in_sizes, int n_in,
                              void* d_out, int out_size) {
    const float* mean        = (const float*)d_in[0];
    const float* cov         = (const float*)d_in[1];
    const int*   edge_index  = (const int*)  d_in[2];
    const float* W_mean      = (const float*)d_in[3];
    const float* att_src_m   = (const float*)d_in[4];
    const float* att_dst_m   = (const float*)d_in[5];
    const float* bias_mean   = (const float*)d_in[6];
    const float* W_cov       = (const float*)d_in[7];
    const float* att_src_c   = (const float*)d_in[8];
    const float* att_dst_c   = (const float*)d_in[9];
    const float* bias_cov    = (const float*)d_in[10];
    const float* fm_W1       = (const float*)d_in[11];
    const float* fm_b1       = (const float*)d_in[12];
    const float* fm_W2       = (const float*)d_in[13];
    const float* fm_b2       = (const float*)d_in[14];
    const float* fcv_W1      = (const float*)d_in[15];
    const float* fcv_b1      = (const float*)d_in[16];
    const float* fcv_W2      = (const float*)d_in[17];
    const float* fcv_b2      = (const float*)d_in[18];
    float* outp = (float*)d_out;

    cudaFuncSetAttribute(k_mma_cov, cudaFuncAttributeMaxDynamicSharedMemorySize,
                         SG_SMEM_FLOATS * 4);

    // phase 1: input-only work
    k_combo1<<<461, 256>>>(fcv_W1, fcv_W2, W_cov, att_src_c, att_dst_c,
                           fm_W1, fm_W2, fm_b1, fm_b2, bias_mean, W_mean,
                           att_src_m, att_dst_m);

    // phase 2: logits, hist, mean proj, Wfold, bias
    k_combo2<<<12757, 256>>>(mean, cov, edge_index, W_cov,
                             bias_cov, fcv_b1, fcv_W2, fcv_b2);

    // phase 3-4: CSR finalize; scatter emits per-edge exp numerators
    k_scan<<<1, 1024>>>();
    k_scatter<<<(ETOT + 255) / 256, 256>>>(edge_index);

    // phase 5: fused aggregation (R9-proven structure)
    k_agg_fused<<<NN, 320>>>(cov, outp);

    // phase 6: tensor-core projection of z
    dim3 gg(2, (NN + 127) / 128);
    k_mma_cov<<<gg, 256, SG_SMEM_FLOATS * 4>>>(outp + (size_t)NN * 16);
}

// round 13
// speedup vs baseline: 1.4175x; 1.1587x over previous
#include <cuda_runtime.h>
#include <cuda_fp16.h>
#include <cstdint>

#define NN 50000
#define NPAD 50048
#define EE 800000
#define ETOT (EE + NN)

// ---------------- scratch ----------------
__device__ __half g_z[(size_t)NPAD * 1024];   // fp16 (10 mantissa bits == tf32); rows >= NN stay 0
__device__ float  g_xh_mean[(size_t)NN * 64];
__device__ float4 g_srcA[NN * 2];   // [2n]=cov logits (src), [2n+1]=mean logits (src)
__device__ float4 g_dstA[NN * 2];
__device__ float  g_Wc2[256 * 256];
__device__ __half g_BT[256 * 1024]; // fp16 B^T: [c][h*256+j] = 0.25*Wfold[j][h*256+c]
__device__ float  g_Wfold_mean[16 * 64];
__device__ float4 g_wsrc_cov[256], g_wdst_cov[256];
__device__ float4 g_wsrc_mean[16], g_wdst_mean[16];
__device__ float  g_bias_cov_out[256];
__device__ float  g_bias_mean_out[16];
__device__ int    g_counts[NN];
__device__ int    g_offsets[NN + 1];
__device__ int    g_cursor[NN];
__device__ int    g_csr_src[ETOT];
__device__ float4 g_coefC[ETOT];    // exp numerators (cov), per edge, CSR order
__device__ float4 g_coefM[ETOT];    // exp numerators (mean)

__device__ __forceinline__ float lrelu(float x) { return x > 0.f ? x : 0.2f * x; }

__device__ __forceinline__ void wred_sum4(float4& v) {
#pragma unroll
    for (int o = 16; o; o >>= 1) {
        v.x += __shfl_xor_sync(0xffffffffu, v.x, o);
        v.y += __shfl_xor_sync(0xffffffffu, v.y, o);
        v.z += __shfl_xor_sync(0xffffffffu, v.z, o);
        v.w += __shfl_xor_sync(0xffffffffu, v.w, o);
    }
}

// ---------------- cp.async / mma helpers ----------------
__device__ __forceinline__ uint32_t smem_u32(const void* p) {
    uint32_t a;
    asm("{ .reg .u64 tmp; cvta.to.shared.u64 tmp, %1; cvt.u32.u64 %0, tmp; }" : "=r"(a) : "l"(p));
    return a;
}
__device__ __forceinline__ void cp16(uint32_t dst, const void* src) {
    asm volatile("cp.async.cg.shared.global [%0], [%1], 16;" :: "r"(dst), "l"(src));
}
#define CP_COMMIT() asm volatile("cp.async.commit_group;" ::: "memory")

// fp16 MMA, fp32 accumulate: D(16x8) += A(16x16,row) * B(16x8,col)
#define MMA_F16(d, a, b) \
    asm volatile("mma.sync.aligned.m16n8k16.row.col.f32.f16.f16.f32 " \
        "{%0,%1,%2,%3}, {%4,%5,%6,%7}, {%8,%9}, {%0,%1,%2,%3};" \
        : "+f"((d)[0]), "+f"((d)[1]), "+f"((d)[2]), "+f"((d)[3]) \
        : "r"((a)[0]), "r"((a)[1]), "r"((a)[2]), "r"((a)[3]), "r"((b)[0]), "r"((b)[1]))

// ================= device-side phase bodies =================

__device__ void body_prep_mean(const float* fmW1, const float* fmW2,
                               const float* fmb1, const float* fmb2,
                               const float* bias_mean, const float* W_mean,
                               const float* att_src, const float* att_dst) {
    __shared__ float Wm2s[16][16];
    int t = threadIdx.x;
    {
        int r = t >> 4, c = t & 15;
        float s = 0.f;
        for (int k = 0; k < 16; k++) s += fmW1[r * 16 + k] * fmW2[k * 16 + c];
        Wm2s[r][c] = s;
    }
    if (t < 128) {
        int sd = t >> 6, rem = t & 63, r = rem >> 2, h = rem & 3;
        const float* att = sd ? att_dst : att_src;
        float s = 0.f;
        for (int j = 0; j < 16; j++) s += W_mean[r * 64 + h * 16 + j] * att[h * 16 + j];
        float* dstp = sd ? (float*)g_wdst_mean : (float*)g_wsrc_mean;
        dstp[r * 4 + h] = s;
    }
    __syncthreads();
    if (t < 16) {
        float b = fmb2[t];
        for (int k = 0; k < 16; k++)
            b += bias_mean[k] * Wm2s[k][t] + fmb1[k] * fmW2[k * 16 + t];
        g_bias_mean_out[t] = b;
    }
    for (int o = t; o < 1024; o += 256) {
        int r = o >> 6, hc = o & 63, h = hc >> 4, c = hc & 15;
        float s = 0.f;
        for (int j = 0; j < 16; j++) s += W_mean[r * 64 + h * 16 + j] * Wm2s[j][c];
        g_Wfold_mean[o] = s;
    }
}

__device__ void body_Wc2(int vb, const float* W1, const float* W2) {
    int r = vb, c = threadIdx.x;
    float s = 0.f;
    for (int k = 0; k < 256; k++) s += W1[r * 256 + k] * W2[k * 256 + c];
    g_Wc2[r * 256 + c] = s;
}

__device__ void body_att_cov(int vb, const float* W_cov, const float* att_src,
                             const float* att_dst) {
    int o = vb * 256 + threadIdx.x;
    int sd = o >> 10, rem = o & 1023, r = rem >> 2, h = rem & 3;
    const float* att = sd ? att_dst : att_src;
    const float* wrow = W_cov + (size_t)r * 1024 + h * 256;
    float s = 0.f;
    for (int j = 0; j < 256; j++) s += wrow[j] * att[h * 256 + j];
    float* dstp = sd ? (float*)g_wdst_cov : (float*)g_wsrc_cov;
    dstp[r * 4 + h] = s;
}

__device__ void body_init_counts(int vb) {
    int i = vb * 256 + threadIdx.x;
    if (i < NN) g_counts[i] = 1;
}

__device__ void body_bias_cov(const float* bias_cov, const float* fb1,
                              const float* fW2, const float* fb2) {
    int c = threadIdx.x;
    float b = fb2[c];
    for (int k = 0; k < 256; k++)
        b += bias_cov[k] * g_Wc2[k * 256 + c] + fb1[k] * fW2[k * 256 + c];
    g_bias_cov_out[c] = b;
}

__device__ void body_Wfold_cov(int vb, const float* W_cov) {
    __shared__ float wc2s[32][256];
    __shared__ float wr[4][256];
    int seg = vb & 3, r0 = (vb >> 2) * 4;
    int t = threadIdx.x;
    float acc[4];
#pragma unroll
    for (int i = 0; i < 4; i++) acc[i] = 0.f;
#pragma unroll
    for (int i = 0; i < 4; i++)
        wr[i][t] = W_cov[(size_t)(r0 + i) * 1024 + seg * 256 + t];
    __syncthreads();
    for (int j0 = 0; j0 < 256; j0 += 32) {
        for (int i = 0; i < 32; i++)
            wc2s[i][t] = g_Wc2[(size_t)(j0 + i) * 256 + t];
        __syncthreads();
#pragma unroll
        for (int jj = 0; jj < 32; jj++) {
            float b = wc2s[jj][t];
#pragma unroll
            for (int i = 0; i < 4; i++) acc[i] += wr[i][j0 + jj] * b;
        }
        __syncthreads();
    }
#pragma unroll
    for (int i = 0; i < 4; i++)
        g_BT[(size_t)t * 1024 + seg * 256 + r0 + i] = __float2half_rn(0.25f * acc[i]);
}

__device__ void body_hist(int vb, const int* ei) {
    int e = vb * 256 + threadIdx.x;
    if (e < EE) atomicAdd(&g_counts[ei[EE + e]], 1);
}

__device__ void body_a(int vb, const float* mean, const float* cov) {
    int warp = threadIdx.x >> 5, lane = threadIdx.x & 31;
    int n = vb * 8 + warp;
    if (n >= NN) return;
    const float* x = cov + (size_t)n * 256;
    float4 as = make_float4(0, 0, 0, 0), ad = make_float4(0, 0, 0, 0);
    for (int r = lane; r < 256; r += 32) {
        float xv = __ldg(x + r);
        float4 ws = g_wsrc_cov[r], wd = g_wdst_cov[r];
        as.x += xv * ws.x; as.y += xv * ws.y; as.z += xv * ws.z; as.w += xv * ws.w;
        ad.x += xv * wd.x; ad.y += xv * wd.y; ad.z += xv * wd.z; ad.w += xv * wd.w;
    }
    wred_sum4(as); wred_sum4(ad);
    float4 ms = make_float4(0, 0, 0, 0), md = make_float4(0, 0, 0, 0);
    if (lane < 16) {
        float xv = __ldg(mean + (size_t)n * 16 + lane);
        float4 ws = g_wsrc_mean[lane], wd = g_wdst_mean[lane];
        ms = make_float4(xv * ws.x, xv * ws.y, xv * ws.z, xv * ws.w);
        md = make_float4(xv * wd.x, xv * wd.y, xv * wd.z, xv * wd.w);
    }
    wred_sum4(ms); wred_sum4(md);
    if (lane == 0) {
        g_srcA[2 * n]     = as;
        g_srcA[2 * n + 1] = ms;
        g_dstA[2 * n]     = ad;
        g_dstA[2 * n + 1] = md;
    }
}

__device__ void body_gemm_mean(int vb, const float* X) {
    __shared__ float xs[16][16];
    __shared__ float ws[16][64];
    int t = threadIdx.x;
    int row0 = vb * 16;
    xs[t >> 4][t & 15] = X[(size_t)row0 * 16 + t];
    for (int i = t; i < 1024; i += 256) ws[i >> 6][i & 63] = g_Wfold_mean[i];
    __syncthreads();
    int r = t >> 4, cg = (t & 15) << 2;
    float4 acc = make_float4(0, 0, 0, 0);
#pragma unroll
    for (int k = 0; k < 16; k++) {
        float a = xs[r][k];
        acc.x += a * ws[k][cg + 0];
        acc.y += a * ws[k][cg + 1];
        acc.z += a * ws[k][cg + 2];
        acc.w += a * ws[k][cg + 3];
    }
    *(float4*)(g_xh_mean + (size_t)(row0 + r) * 64 + cg) = acc;
}

// ================= combo kernels =================

__global__ void __launch_bounds__(256) k_combo1(
    const float* __restrict__ fcv_W1, const float* __restrict__ fcv_W2,
    const float* __restrict__ W_cov, const float* __restrict__ att_src_c,
    const float* __restrict__ att_dst_c,
    const float* __restrict__ fm_W1, const float* __restrict__ fm_W2,
    const float* __restrict__ fm_b1, const float* __restrict__ fm_b2,
    const float* __restrict__ bias_mean, const float* __restrict__ W_mean,
    const float* __restrict__ att_src_m, const float* __restrict__ att_dst_m) {
    int b = blockIdx.x;
    if (b < 256)       body_Wc2(b, fcv_W1, fcv_W2);
    else if (b < 452)  body_init_counts(b - 256);
    else if (b < 460)  body_att_cov(b - 452, W_cov, att_src_c, att_dst_c);
    else               body_prep_mean(fm_W1, fm_W2, fm_b1, fm_b2, bias_mean,
                                      W_mean, att_src_m, att_dst_m);
}

__global__ void __launch_bounds__(256) k_combo2(
    const float* __restrict__ mean, const float* __restrict__ cov,
    const int* __restrict__ ei, const float* __restrict__ W_cov,
    const float* __restrict__ bias_cov, const float* __restrict__ fcv_b1,
    const float* __restrict__ fcv_W2, const float* __restrict__ fcv_b2) {
    int b = blockIdx.x;
    if (b < 6250)        body_a(b, mean, cov);
    else if (b < 9375)   body_hist(b - 6250, ei);
    else if (b < 12500)  body_gemm_mean(b - 9375, mean);
    else if (b < 12756)  body_Wfold_cov(b - 12500, W_cov);
    else                 body_bias_cov(bias_cov, fcv_b1, fcv_W2, fcv_b2);
}

// ---------------- scan ----------------
__global__ void k_scan() {
    __shared__ int ssum[1024];
    int t = threadIdx.x;
    const int PER = (NN + 1023) / 1024;
    int base = t * PER;
    int local = 0;
    for (int i = 0; i < PER; i++) { int idx = base + i; if (idx < NN) local += g_counts[idx]; }
    ssum[t] = local;
    __syncthreads();
    for (int off = 1; off < 1024; off <<= 1) {
        int v = (t >= off) ? ssum[t - off] : 0;
        __syncthreads();
        ssum[t] += v;
        __syncthreads();
    }
    int prefix = (t == 0) ? 0 : ssum[t - 1];
    for (int i = 0; i < PER; i++) {
        int idx = base + i;
        if (idx < NN) {
            g_offsets[idx] = prefix;
            g_cursor[idx] = prefix;
            prefix += g_counts[idx];
        }
    }
    if (t == 1023) g_offsets[NN] = ssum[1023];
}

// scatter: CSR ids + per-edge exp numerators
__global__ void k_scatter(const int* __restrict__ ei) {
    int e = blockIdx.x * 256 + threadIdx.x;
    if (e >= ETOT) return;
    int s, d;
    if (e < EE) { s = ei[e]; d = ei[EE + e]; }
    else        { s = e - EE; d = s; }
    int pos = atomicAdd(&g_cursor[d], 1);
    g_csr_src[pos] = s;
    float4 ac = g_srcA[2 * s], dc = g_dstA[2 * d];
    g_coefC[pos] = make_float4(__expf(lrelu(ac.x + dc.x)), __expf(lrelu(ac.y + dc.y)),
                               __expf(lrelu(ac.z + dc.z)), __expf(lrelu(ac.w + dc.w)));
    float4 am = g_srcA[2 * s + 1], dm = g_dstA[2 * d + 1];
    g_coefM[pos] = make_float4(__expf(lrelu(am.x + dm.x)), __expf(lrelu(am.y + dm.y)),
                               __expf(lrelu(am.z + dm.z)), __expf(lrelu(am.w + dm.w)));
}

// ---------------- fused aggregation (R9-proven; z output now fp16) ----------------
__global__ void __launch_bounds__(320) k_agg_fused(const float* __restrict__ cov,
                                                   float* __restrict__ out_mean) {
    __shared__ float4 cfs[256];
    __shared__ float4 cfm[256];
    __shared__ int    srcs[256];
    __shared__ float4 s_invc, s_invm;
    __shared__ float  mred[64];
    int dst = blockIdx.x;
    int t = threadIdx.x;
    int warp = t >> 5, lane = t & 31;
    int beg = g_offsets[dst];
    int deg = g_offsets[dst + 1] - beg;

    if (warp == 0) {
        float4 sc = make_float4(0, 0, 0, 0);
        for (int j = lane; j < deg; j += 32) {
            float4 c = g_coefC[beg + j];
            sc.x += c.x; sc.y += c.y; sc.z += c.z; sc.w += c.w;
        }
        wred_sum4(sc);
        if (lane == 0)
            s_invc = make_float4(1.f / (sc.x + 1e-16f), 1.f / (sc.y + 1e-16f),
                                 1.f / (sc.z + 1e-16f), 1.f / (sc.w + 1e-16f));
    } else if (warp == 8) {
        float4 sm = make_float4(0, 0, 0, 0);
        for (int j = lane; j < deg; j += 32) {
            float4 c = g_coefM[beg + j];
            sm.x += c.x; sm.y += c.y; sm.z += c.z; sm.w += c.w;
        }
        wred_sum4(sm);
        if (lane == 0)
            s_invm = make_float4(1.f / (sm.x + 1e-16f), 1.f / (sm.y + 1e-16f),
                                 1.f / (sm.z + 1e-16f), 1.f / (sm.w + 1e-16f));
    }
    __syncthreads();

    float a0 = 0.f, a1 = 0.f, a2 = 0.f, a3 = 0.f;
    float accm = 0.f;
    int mh = (t - 256) >> 4, mc = (t - 256) & 15;

    for (int c0 = 0; c0 < deg; c0 += 256) {
        int cnt = min(256, deg - c0);
        if (t < cnt) {
            srcs[t] = g_csr_src[beg + c0 + t];
            float4 c = g_coefC[beg + c0 + t];
            cfs[t] = make_float4(c.x * s_invc.x, c.y * s_invc.y,
                                 c.z * s_invc.z, c.w * s_invc.w);
            float4 m = g_coefM[beg + c0 + t];
            cfm[t] = make_float4(m.x * s_invm.x, m.y * s_invm.y,
                                 m.z * s_invm.z, m.w * s_invm.w);
        }
        __syncthreads();
        if (t < 256) {
#pragma unroll 4
            for (int j = 0; j < cnt; j++) {
                float4 cf = cfs[j];
                float v = __ldg(cov + (size_t)srcs[j] * 256 + t);
                a0 += cf.x * v; a1 += cf.y * v; a2 += cf.z * v; a3 += cf.w * v;
            }
        } else {
#pragma unroll 4
            for (int j = 0; j < cnt; j++) {
                const float* cf = (const float*)&cfm[j];
                accm += cf[mh] * __ldg(g_xh_mean + (size_t)srcs[j] * 64 + mh * 16 + mc);
            }
        }
        __syncthreads();
    }

    if (t < 256) {
        __half* zp = g_z + (size_t)dst * 1024 + t;
        zp[0]   = __float2half_rn(a0);
        zp[256] = __float2half_rn(a1);
        zp[512] = __float2half_rn(a2);
        zp[768] = __float2half_rn(a3);
    } else {
        mred[t - 256] = accm;
    }
    __syncthreads();
    if (t < 16)
        out_mean[(size_t)dst * 16 + t] =
            0.25f * (mred[t] + mred[16 + t] + mred[32 + t] + mred[48 + t])
            + g_bias_mean_out[t];
}

// ---------------- fp16 mma.sync GEMM: out = z[50000,1024] @ BT^T + bias ----------------
// BM=BN=128, BK=32 halves; 8 warps 2x4; warp tile 64x32; m16n8k16.f16.f32.
// smem row stride 40 halves (80B = 20 banks): fragment banks tq*20+tr all distinct mod 32.
#define SH_STRIDE 40
#define SH_BUFSZ  (128 * SH_STRIDE)          // halves per buffer
#define SH_SMEM_BYTES (SH_BUFSZ * 2 * 4)     // A0,A1,B0,B1 = 40960 B
__global__ void __launch_bounds__(256) k_mma_cov(float* __restrict__ out) {
    extern __shared__ __half smh[];
    uint32_t sbase = smem_u32(smh);
    int t = threadIdx.x, wid = t >> 5, lane = t & 31;
    int tq = lane >> 2, tr = lane & 3;
    int bm = blockIdx.y * 128;
    int bn = blockIdx.x * 128;
    int wm = (wid >> 2) * 64;
    int wn = (wid & 3) * 32;

    float acc[4][4][4];
#pragma unroll
    for (int mi = 0; mi < 4; mi++)
#pragma unroll
        for (int ni = 0; ni < 4; ni++)
#pragma unroll
            for (int q = 0; q < 4; q++) acc[mi][ni][q] = 0.f;

    auto stage = [&](int c, int buf) {
        int kc = c * 32;
        uint32_t aoff = sbase + (uint32_t)(buf * SH_BUFSZ) * 2;
        uint32_t boff = sbase + (uint32_t)((2 + buf) * SH_BUFSZ) * 2;
        // A: 128 rows x 32 halves = 512 chunks of 8 halves (16B); 2 per thread
#pragma unroll
        for (int i = 0; i < 2; i++) {
            int f = i * 256 + t;
            int r = f >> 2, q = f & 3;
            const __half* src = g_z + (size_t)(bm + r) * 1024 + kc + q * 8;  // NPAD: no guard
            cp16(aoff + (uint32_t)(r * SH_STRIDE + q * 8) * 2, src);
        }
#pragma unroll
        for (int i = 0; i < 2; i++) {
            int f = i * 256 + t;
            int r = f >> 2, q = f & 3;
            const __half* src = g_BT + (size_t)(bn + r) * 1024 + kc + q * 8;
            cp16(boff + (uint32_t)(r * SH_STRIDE + q * 8) * 2, src);
        }
        CP_COMMIT();
    };

    stage(0, 0);
    for (int c = 0; c < 32; c++) {
        int buf = c & 1;
        if (c < 31) {
            stage(c + 1, (c + 1) & 1);
            asm volatile("cp.async.wait_group 1;" ::: "memory");
        } else {
            asm volatile("cp.async.wait_group 0;" ::: "memory");
        }
        __syncthreads();
        const __half* As = smh + buf * SH_BUFSZ;
        const __half* Bs = smh + (2 + buf) * SH_BUFSZ;
#pragma unroll
        for (int kk = 0; kk < 2; kk++) {
            int k16 = kk * 16;
            uint32_t af[4][4], bf[4][2];
#pragma unroll
            for (int mi = 0; mi < 4; mi++) {
                int row = wm + mi * 16 + tq;
                const __half* ap = As + row * SH_STRIDE + k16 + 2 * tr;
                af[mi][0] = *(const uint32_t*)ap;
                af[mi][1] = *(const uint32_t*)(ap + 8 * SH_STRIDE);
                af[mi][2] = *(const uint32_t*)(ap + 8);
                af[mi][3] = *(const uint32_t*)(ap + 8 * SH_STRIDE + 8);
            }
#pragma unroll
            for (int ni = 0; ni < 4; ni++) {
                int col = wn + ni * 8 + tq;
                const __half* bp = Bs + col * SH_STRIDE + k16 + 2 * tr;
                bf[ni][0] = *(const uint32_t*)bp;
                bf[ni][1] = *(const uint32_t*)(bp + 8);
            }
#pragma unroll
            for (int mi = 0; mi < 4; mi++)
#pragma unroll
                for (int ni = 0; ni < 4; ni++)
                    MMA_F16(acc[mi][ni], af[mi], bf[ni]);
        }
        __syncthreads();
    }

#pragma unroll
    for (int mi = 0; mi < 4; mi++) {
#pragma unroll
        for (int ni = 0; ni < 4; ni++) {
            int cc = bn + wn + ni * 8 + 2 * tr;
            float b0 = g_bias_cov_out[cc], b1 = g_bias_cov_out[cc + 1];
            int r0 = bm + wm + mi * 16 + tq;
            if (r0 < NN) {
                float2 v = make_float2(acc[mi][ni][0] + b0, acc[mi][ni][1] + b1);
                *(float2*)(out + (size_t)r0 * 256 + cc) = v;
            }
            int r1 = r0 + 8;
            if (r1 < NN) {
                float2 v = make_float2(acc[mi][ni][2] + b0, acc[mi][ni][3] + b1);
                *(float2*)(out + (size_t)r1 * 256 + cc) = v;
            }
        }
    }
}

// ---------------- launch ----------------
extern "C" void kernel_launch(void* const* d_in, const int* in_sizes, int n_in,
                              void* d_out, int out_size) {
    const float* mean        = (const float*)d_in[0];
    const float* cov         = (const float*)d_in[1];
    const int*   edge_index  = (const int*)  d_in[2];
    const float* W_mean      = (const float*)d_in[3];
    const float* att_src_m   = (const float*)d_in[4];
    const float* att_dst_m   = (const float*)d_in[5];
    const float* bias_mean   = (const float*)d_in[6];
    const float* W_cov       = (const float*)d_in[7];
    const float* att_src_c   = (const float*)d_in[8];
    const float* att_dst_c   = (const float*)d_in[9];
    const float* bias_cov    = (const float*)d_in[10];
    const float* fm_W1       = (const float*)d_in[11];
    const float* fm_b1       = (const float*)d_in[12];
    const float* fm_W2       = (const float*)d_in[13];
    const float* fm_b2       = (const float*)d_in[14];
    const float* fcv_W1      = (const float*)d_in[15];
    const float* fcv_b1      = (const float*)d_in[16];
    const float* fcv_W2      = (const float*)d_in[17];
    const float* fcv_b2      = (const float*)d_in[18];
    float* outp = (float*)d_out;

    cudaFuncSetAttribute(k_mma_cov, cudaFuncAttributeMaxDynamicSharedMemorySize,
                         SH_SMEM_BYTES);

    // phase 1: input-only work
    k_combo1<<<461, 256>>>(fcv_W1, fcv_W2, W_cov, att_src_c, att_dst_c,
                           fm_W1, fm_W2, fm_b1, fm_b2, bias_mean, W_mean,
                           att_src_m, att_dst_m);

    // phase 2: logits, hist, mean proj, Wfold, bias
    k_combo2<<<12757, 256>>>(mean, cov, edge_index, W_cov,
                             bias_cov, fcv_b1, fcv_W2, fcv_b2);

    // phase 3-4: CSR finalize; scatter emits per-edge exp numerators
    k_scan<<<1, 1024>>>();
    k_scatter<<<(ETOT + 255) / 256, 256>>>(edge_index);

    // phase 5: fused aggregation (z written as fp16)
    k_agg_fused<<<NN, 320>>>(cov, outp);

    // phase 6: fp16 tensor-core projection of z
    dim3 gg(2, (NN + 127) / 128);
    k_mma_cov<<<gg, 256, SH_SMEM_BYTES>>>(outp + (size_t)NN * 16);
}

// round 17
// speedup vs baseline: 1.5128x; 1.0673x over previous
#include <cuda_runtime.h>
#include <cuda_fp16.h>
#include <cstdint>

#define NN 50000
#define NPAD 50048
#define EE 800000
#define ETOT (EE + NN)

// ---------------- scratch ----------------
__device__ __half g_z[(size_t)NPAD * 1024];   // fp16; rows >= NN stay 0 (.bss)
__device__ __half g_cov_h[(size_t)NN * 256];  // fp16 shadow of cov input (agg gather)
__device__ float  g_xh_mean[(size_t)NN * 64];
__device__ float4 g_srcA[NN * 2];
__device__ float4 g_dstA[NN * 2];
__device__ float  g_Wc2[256 * 256];
__device__ __half g_BT[256 * 1024];
__device__ float  g_Wfold_mean[16 * 64];
__device__ float4 g_wsrc_cov[256], g_wdst_cov[256];
__device__ float4 g_wsrc_mean[16], g_wdst_mean[16];
__device__ float  g_bias_cov_out[256];
__device__ float  g_bias_mean_out[16];
__device__ int    g_counts[NN];
__device__ int    g_offsets[NN + 1];
__device__ int    g_cursor[NN];
__device__ int    g_csr_src[ETOT];
__device__ float4 g_coefC[ETOT];
__device__ float4 g_coefM[ETOT];

__device__ __forceinline__ float lrelu(float x) { return x > 0.f ? x : 0.2f * x; }

__device__ __forceinline__ void wred_sum4(float4& v) {
#pragma unroll
    for (int o = 16; o; o >>= 1) {
        v.x += __shfl_xor_sync(0xffffffffu, v.x, o);
        v.y += __shfl_xor_sync(0xffffffffu, v.y, o);
        v.z += __shfl_xor_sync(0xffffffffu, v.z, o);
        v.w += __shfl_xor_sync(0xffffffffu, v.w, o);
    }
}

// ---------------- cp.async / mma helpers ----------------
__device__ __forceinline__ uint32_t smem_u32(const void* p) {
    uint32_t a;
    asm("{ .reg .u64 tmp; cvta.to.shared.u64 tmp, %1; cvt.u32.u64 %0, tmp; }" : "=r"(a) : "l"(p));
    return a;
}
__device__ __forceinline__ void cp16(uint32_t dst, const void* src) {
    asm volatile("cp.async.cg.shared.global [%0], [%1], 16;" :: "r"(dst), "l"(src));
}
#define CP_COMMIT() asm volatile("cp.async.commit_group;" ::: "memory")

#define MMA_F16(d, a, b) \
    asm volatile("mma.sync.aligned.m16n8k16.row.col.f32.f16.f16.f32 " \
        "{%0,%1,%2,%3}, {%4,%5,%6,%7}, {%8,%9}, {%0,%1,%2,%3};" \
        : "+f"((d)[0]), "+f"((d)[1]), "+f"((d)[2]), "+f"((d)[3]) \
        : "r"((a)[0]), "r"((a)[1]), "r"((a)[2]), "r"((a)[3]), "r"((b)[0]), "r"((b)[1]))

// ================= device-side phase bodies =================

__device__ void body_prep_mean(const float* fmW1, const float* fmW2,
                               const float* fmb1, const float* fmb2,
                               const float* bias_mean, const float* W_mean,
                               const float* att_src, const float* att_dst) {
    __shared__ float Wm2s[16][16];
    int t = threadIdx.x;
    {
        int r = t >> 4, c = t & 15;
        float s = 0.f;
        for (int k = 0; k < 16; k++) s += fmW1[r * 16 + k] * fmW2[k * 16 + c];
        Wm2s[r][c] = s;
    }
    if (t < 128) {
        int sd = t >> 6, rem = t & 63, r = rem >> 2, h = rem & 3;
        const float* att = sd ? att_dst : att_src;
        float s = 0.f;
        for (int j = 0; j < 16; j++) s += W_mean[r * 64 + h * 16 + j] * att[h * 16 + j];
        float* dstp = sd ? (float*)g_wdst_mean : (float*)g_wsrc_mean;
        dstp[r * 4 + h] = s;
    }
    __syncthreads();
    if (t < 16) {
        float b = fmb2[t];
        for (int k = 0; k < 16; k++)
            b += bias_mean[k] * Wm2s[k][t] + fmb1[k] * fmW2[k * 16 + t];
        g_bias_mean_out[t] = b;
    }
    for (int o = t; o < 1024; o += 256) {
        int r = o >> 6, hc = o & 63, h = hc >> 4, c = hc & 15;
        float s = 0.f;
        for (int j = 0; j < 16; j++) s += W_mean[r * 64 + h * 16 + j] * Wm2s[j][c];
        g_Wfold_mean[o] = s;
    }
}

__device__ void body_Wc2(int vb, const float* W1, const float* W2) {
    int r = vb, c = threadIdx.x;
    float s = 0.f;
    for (int k = 0; k < 256; k++) s += W1[r * 256 + k] * W2[k * 256 + c];
    g_Wc2[r * 256 + c] = s;
}

__device__ void body_att_cov(int vb, const float* W_cov, const float* att_src,
                             const float* att_dst) {
    int o = vb * 256 + threadIdx.x;
    int sd = o >> 10, rem = o & 1023, r = rem >> 2, h = rem & 3;
    const float* att = sd ? att_dst : att_src;
    const float* wrow = W_cov + (size_t)r * 1024 + h * 256;
    float s = 0.f;
    for (int j = 0; j < 256; j++) s += wrow[j] * att[h * 256 + j];
    float* dstp = sd ? (float*)g_wdst_cov : (float*)g_wsrc_cov;
    dstp[r * 4 + h] = s;
}

__device__ void body_init_counts(int vb) {
    int i = vb * 256 + threadIdx.x;
    if (i < NN) g_counts[i] = 1;
}

// fp16 shadow of cov: 6250 blocks x 2048 elements
__device__ void body_covh(int vb, const float* cov) {
    size_t base = (size_t)vb * 2048 + threadIdx.x;
#pragma unroll
    for (int i = 0; i < 8; i++) {
        size_t idx = base + (size_t)i * 256;
        g_cov_h[idx] = __float2half_rn(cov[idx]);
    }
}

__device__ void body_bias_cov(const float* bias_cov, const float* fb1,
                              const float* fW2, const float* fb2) {
    int c = threadIdx.x;
    float b = fb2[c];
    for (int k = 0; k < 256; k++)
        b += bias_cov[k] * g_Wc2[k * 256 + c] + fb1[k] * fW2[k * 256 + c];
    g_bias_cov_out[c] = b;
}

__device__ void body_Wfold_cov(int vb, const float* W_cov) {
    __shared__ float wc2s[32][256];
    __shared__ float wr[4][256];
    int seg = vb & 3, r0 = (vb >> 2) * 4;
    int t = threadIdx.x;
    float acc[4];
#pragma unroll
    for (int i = 0; i < 4; i++) acc[i] = 0.f;
#pragma unroll
    for (int i = 0; i < 4; i++)
        wr[i][t] = W_cov[(size_t)(r0 + i) * 1024 + seg * 256 + t];
    __syncthreads();
    for (int j0 = 0; j0 < 256; j0 += 32) {
        for (int i = 0; i < 32; i++)
            wc2s[i][t] = g_Wc2[(size_t)(j0 + i) * 256 + t];
        __syncthreads();
#pragma unroll
        for (int jj = 0; jj < 32; jj++) {
            float b = wc2s[jj][t];
#pragma unroll
            for (int i = 0; i < 4; i++) acc[i] += wr[i][j0 + jj] * b;
        }
        __syncthreads();
    }
#pragma unroll
    for (int i = 0; i < 4; i++)
        g_BT[(size_t)t * 1024 + seg * 256 + r0 + i] = __float2half_rn(0.25f * acc[i]);
}

__device__ void body_hist(int vb, const int* ei) {
    int e = vb * 256 + threadIdx.x;
    if (e < EE) atomicAdd(&g_counts[ei[EE + e]], 1);
}

__device__ void body_a(int vb, const float* mean, const float* cov) {
    int warp = threadIdx.x >> 5, lane = threadIdx.x & 31;
    int n = vb * 8 + warp;
    if (n >= NN) return;
    const float* x = cov + (size_t)n * 256;
    float4 as = make_float4(0, 0, 0, 0), ad = make_float4(0, 0, 0, 0);
    for (int r = lane; r < 256; r += 32) {
        float xv = __ldg(x + r);
        float4 ws = g_wsrc_cov[r], wd = g_wdst_cov[r];
        as.x += xv * ws.x; as.y += xv * ws.y; as.z += xv * ws.z; as.w += xv * ws.w;
        ad.x += xv * wd.x; ad.y += xv * wd.y; ad.z += xv * wd.z; ad.w += xv * wd.w;
    }
    wred_sum4(as); wred_sum4(ad);
    float4 ms = make_float4(0, 0, 0, 0), md = make_float4(0, 0, 0, 0);
    if (lane < 16) {
        float xv = __ldg(mean + (size_t)n * 16 + lane);
        float4 ws = g_wsrc_mean[lane], wd = g_wdst_mean[lane];
        ms = make_float4(xv * ws.x, xv * ws.y, xv * ws.z, xv * ws.w);
        md = make_float4(xv * wd.x, xv * wd.y, xv * wd.z, xv * wd.w);
    }
    wred_sum4(ms); wred_sum4(md);
    if (lane == 0) {
        g_srcA[2 * n]     = as;
        g_srcA[2 * n + 1] = ms;
        g_dstA[2 * n]     = ad;
        g_dstA[2 * n + 1] = md;
    }
}

__device__ void body_gemm_mean(int vb, const float* X) {
    __shared__ float xs[16][16];
    __shared__ float ws[16][64];
    int t = threadIdx.x;
    int row0 = vb * 16;
    xs[t >> 4][t & 15] = X[(size_t)row0 * 16 + t];
    for (int i = t; i < 1024; i += 256) ws[i >> 6][i & 63] = g_Wfold_mean[i];
    __syncthreads();
    int r = t >> 4, cg = (t & 15) << 2;
    float4 acc = make_float4(0, 0, 0, 0);
#pragma unroll
    for (int k = 0; k < 16; k++) {
        float a = xs[r][k];
        acc.x += a * ws[k][cg + 0];
        acc.y += a * ws[k][cg + 1];
        acc.z += a * ws[k][cg + 2];
        acc.w += a * ws[k][cg + 3];
    }
    *(float4*)(g_xh_mean + (size_t)(row0 + r) * 64 + cg) = acc;
}

// ================= combo kernels =================

// combo1: [Wc2: 0..255][init: 256..451][att_cov: 452..459][prep_mean: 460][covh: 461..6710]
__global__ void __launch_bounds__(256) k_combo1(
    const float* __restrict__ fcv_W1, const float* __restrict__ fcv_W2,
    const float* __restrict__ W_cov, const float* __restrict__ att_src_c,
    const float* __restrict__ att_dst_c,
    const float* __restrict__ fm_W1, const float* __restrict__ fm_W2,
    const float* __restrict__ fm_b1, const float* __restrict__ fm_b2,
    const float* __restrict__ bias_mean, const float* __restrict__ W_mean,
    const float* __restrict__ att_src_m, const float* __restrict__ att_dst_m,
    const float* __restrict__ cov) {
    int b = blockIdx.x;
    if (b < 256)       body_Wc2(b, fcv_W1, fcv_W2);
    else if (b < 452)  body_init_counts(b - 256);
    else if (b < 460)  body_att_cov(b - 452, W_cov, att_src_c, att_dst_c);
    else if (b == 460) body_prep_mean(fm_W1, fm_W2, fm_b1, fm_b2, bias_mean,
                                      W_mean, att_src_m, att_dst_m);
    else               body_covh(b - 461, cov);
}

__global__ void __launch_bounds__(256) k_combo2(
    const float* __restrict__ mean, const float* __restrict__ cov,
    const int* __restrict__ ei, const float* __restrict__ W_cov,
    const float* __restrict__ bias_cov, const float* __restrict__ fcv_b1,
    const float* __restrict__ fcv_W2, const float* __restrict__ fcv_b2) {
    int b = blockIdx.x;
    if (b < 6250)        body_a(b, mean, cov);
    else if (b < 9375)   body_hist(b - 6250, ei);
    else if (b < 12500)  body_gemm_mean(b - 9375, mean);
    else if (b < 12756)  body_Wfold_cov(b - 12500, W_cov);
    else                 body_bias_cov(bias_cov, fcv_b1, fcv_W2, fcv_b2);
}

// ---------------- scan ----------------
__global__ void k_scan() {
    __shared__ int ssum[1024];
    int t = threadIdx.x;
    const int PER = (NN + 1023) / 1024;
    int base = t * PER;
    int local = 0;
    for (int i = 0; i < PER; i++) { int idx = base + i; if (idx < NN) local += g_counts[idx]; }
    ssum[t] = local;
    __syncthreads();
    for (int off = 1; off < 1024; off <<= 1) {
        int v = (t >= off) ? ssum[t - off] : 0;
        __syncthreads();
        ssum[t] += v;
        __syncthreads();
    }
    int prefix = (t == 0) ? 0 : ssum[t - 1];
    for (int i = 0; i < PER; i++) {
        int idx = base + i;
        if (idx < NN) {
            g_offsets[idx] = prefix;
            g_cursor[idx] = prefix;
            prefix += g_counts[idx];
        }
    }
    if (t == 1023) g_offsets[NN] = ssum[1023];
}

// scatter: CSR ids + per-edge exp numerators
__global__ void k_scatter(const int* __restrict__ ei) {
    int e = blockIdx.x * 256 + threadIdx.x;
    if (e >= ETOT) return;
    int s, d;
    if (e < EE) { s = ei[e]; d = ei[EE + e]; }
    else        { s = e - EE; d = s; }
    int pos = atomicAdd(&g_cursor[d], 1);
    g_csr_src[pos] = s;
    float4 ac = g_srcA[2 * s], dc = g_dstA[2 * d];
    g_coefC[pos] = make_float4(__expf(lrelu(ac.x + dc.x)), __expf(lrelu(ac.y + dc.y)),
                               __expf(lrelu(ac.z + dc.z)), __expf(lrelu(ac.w + dc.w)));
    float4 am = g_srcA[2 * s + 1], dm = g_dstA[2 * d + 1];
    g_coefM[pos] = make_float4(__expf(lrelu(am.x + dm.x)), __expf(lrelu(am.y + dm.y)),
                               __expf(lrelu(am.z + dm.z)), __expf(lrelu(am.w + dm.w)));
}

// ---------------- fused aggregation (gather fp16 cov shadow) ----------------
__global__ void __launch_bounds__(320) k_agg_fused(float* __restrict__ out_mean) {
    __shared__ float4 cfs[256];
    __shared__ float4 cfm[256];
    __shared__ int    srcs[256];
    __shared__ float4 s_invc, s_invm;
    __shared__ float  mred[64];
    int dst = blockIdx.x;
    int t = threadIdx.x;
    int warp = t >> 5, lane = t & 31;
    int beg = g_offsets[dst];
    int deg = g_offsets[dst + 1] - beg;

    if (warp == 0) {
        float4 sc = make_float4(0, 0, 0, 0);
        for (int j = lane; j < deg; j += 32) {
            float4 c = g_coefC[beg + j];
            sc.x += c.x; sc.y += c.y; sc.z += c.z; sc.w += c.w;
        }
        wred_sum4(sc);
        if (lane == 0)
            s_invc = make_float4(1.f / (sc.x + 1e-16f), 1.f / (sc.y + 1e-16f),
                                 1.f / (sc.z + 1e-16f), 1.f / (sc.w + 1e-16f));
    } else if (warp == 8) {
        float4 sm = make_float4(0, 0, 0, 0);
        for (int j = lane; j < deg; j += 32) {
            float4 c = g_coefM[beg + j];
            sm.x += c.x; sm.y += c.y; sm.z += c.z; sm.w += c.w;
        }
        wred_sum4(sm);
        if (lane == 0)
            s_invm = make_float4(1.f / (sm.x + 1e-16f), 1.f / (sm.y + 1e-16f),
                                 1.f / (sm.z + 1e-16f), 1.f / (sm.w + 1e-16f));
    }
    __syncthreads();

    float a0 = 0.f, a1 = 0.f, a2 = 0.f, a3 = 0.f;
    float accm = 0.f;
    int mh = (t - 256) >> 4, mc = (t - 256) & 15;

    for (int c0 = 0; c0 < deg; c0 += 256) {
        int cnt = min(256, deg - c0);
        if (t < cnt) {
            srcs[t] = g_csr_src[beg + c0 + t];
            float4 c = g_coefC[beg + c0 + t];
            cfs[t] = make_float4(c.x * s_invc.x, c.y * s_invc.y,
                                 c.z * s_invc.z, c.w * s_invc.w);
            float4 m = g_coefM[beg + c0 + t];
            cfm[t] = make_float4(m.x * s_invm.x, m.y * s_invm.y,
                                 m.z * s_invm.z, m.w * s_invm.w);
        }
        __syncthreads();
        if (t < 256) {
#pragma unroll 4
            for (int j = 0; j < cnt; j++) {
                float4 cf = cfs[j];
                float v = __half2float(__ldg(g_cov_h + (size_t)srcs[j] * 256 + t));
                a0 += cf.x * v; a1 += cf.y * v; a2 += cf.z * v; a3 += cf.w * v;
            }
        } else {
#pragma unroll 4
            for (int j = 0; j < cnt; j++) {
                const float* cf = (const float*)&cfm[j];
                accm += cf[mh] * __ldg(g_xh_mean + (size_t)srcs[j] * 64 + mh * 16 + mc);
            }
        }
        __syncthreads();
    }

    if (t < 256) {
        __half* zp = g_z + (size_t)dst * 1024 + t;
        zp[0]   = __float2half_rn(a0);
        zp[256] = __float2half_rn(a1);
        zp[512] = __float2half_rn(a2);
        zp[768] = __float2half_rn(a3);
    } else {
        mred[t - 256] = accm;
    }
    __syncthreads();
    if (t < 16)
        out_mean[(size_t)dst * 16 + t] =
            0.25f * (mred[t] + mred[16 + t] + mred[32 + t] + mred[48 + t])
            + g_bias_mean_out[t];
}

// ---------------- fp16 mma.sync GEMM (R13-proven: BK=32 halves, 32 stages) ----------------
// BM=BN=128; 8 warps 2x4; warp tile 64x32; m16n8k16.f16.f32.
// smem row stride 40 halves (80B = 20 banks): fragment banks tq*20+tr all distinct mod 32.
#define SH_STRIDE 40
#define SH_BUFSZ  (128 * SH_STRIDE)          // halves per buffer
#define SH_SMEM_BYTES (SH_BUFSZ * 2 * 4)     // A0,A1,B0,B1 = 40960 B
__global__ void __launch_bounds__(256) k_mma_cov(float* __restrict__ out) {
    extern __shared__ __half smh[];
    uint32_t sbase = smem_u32(smh);
    int t = threadIdx.x, wid = t >> 5, lane = t & 31;
    int tq = lane >> 2, tr = lane & 3;
    int bm = blockIdx.y * 128;
    int bn = blockIdx.x * 128;
    int wm = (wid >> 2) * 64;
    int wn = (wid & 3) * 32;

    float acc[4][4][4];
#pragma unroll
    for (int mi = 0; mi < 4; mi++)
#pragma unroll
        for (int ni = 0; ni < 4; ni++)
#pragma unroll
            for (int q = 0; q < 4; q++) acc[mi][ni][q] = 0.f;

    auto stage = [&](int c, int buf) {
        int kc = c * 32;
        uint32_t aoff = sbase + (uint32_t)(buf * SH_BUFSZ) * 2;
        uint32_t boff = sbase + (uint32_t)((2 + buf) * SH_BUFSZ) * 2;
        // A: 128 rows x 32 halves = 512 chunks of 8 halves (16B); 2 per thread
#pragma unroll
        for (int i = 0; i < 2; i++) {
            int f = i * 256 + t;
            int r = f >> 2, q = f & 3;
            const __half* src = g_z + (size_t)(bm + r) * 1024 + kc + q * 8;  // NPAD: no guard
            cp16(aoff + (uint32_t)(r * SH_STRIDE + q * 8) * 2, src);
        }
#pragma unroll
        for (int i = 0; i < 2; i++) {
            int f = i * 256 + t;
            int r = f >> 2, q = f & 3;
            const __half* src = g_BT + (size_t)(bn + r) * 1024 + kc + q * 8;
            cp16(boff + (uint32_t)(r * SH_STRIDE + q * 8) * 2, src);
        }
        CP_COMMIT();
    };

    stage(0, 0);
    for (int c = 0; c < 32; c++) {
        int buf = c & 1;
        if (c < 31) {
            stage(c + 1, (c + 1) & 1);
            asm volatile("cp.async.wait_group 1;" ::: "memory");
        } else {
            asm volatile("cp.async.wait_group 0;" ::: "memory");
        }
        __syncthreads();
        const __half* As = smh + buf * SH_BUFSZ;
        const __half* Bs = smh + (2 + buf) * SH_BUFSZ;
#pragma unroll
        for (int kk = 0; kk < 2; kk++) {
            int k16 = kk * 16;
            uint32_t af[4][4], bf[4][2];
#pragma unroll
            for (int mi = 0; mi < 4; mi++) {
                int row = wm + mi * 16 + tq;
                const __half* ap = As + row * SH_STRIDE + k16 + 2 * tr;
                af[mi][0] = *(const uint32_t*)ap;
                af[mi][1] = *(const uint32_t*)(ap + 8 * SH_STRIDE);
                af[mi][2] = *(const uint32_t*)(ap + 8);
                af[mi][3] = *(const uint32_t*)(ap + 8 * SH_STRIDE + 8);
            }
#pragma unroll
            for (int ni = 0; ni < 4; ni++) {
                int col = wn + ni * 8 + tq;
                const __half* bp = Bs + col * SH_STRIDE + k16 + 2 * tr;
                bf[ni][0] = *(const uint32_t*)bp;
                bf[ni][1] = *(const uint32_t*)(bp + 8);
            }
#pragma unroll
            for (int mi = 0; mi < 4; mi++)
#pragma unroll
                for (int ni = 0; ni < 4; ni++)
                    MMA_F16(acc[mi][ni], af[mi], bf[ni]);
        }
        __syncthreads();
    }

#pragma unroll
    for (int mi = 0; mi < 4; mi++) {
#pragma unroll
        for (int ni = 0; ni < 4; ni++) {
            int cc = bn + wn + ni * 8 + 2 * tr;
            float b0 = g_bias_cov_out[cc], b1 = g_bias_cov_out[cc + 1];
            int r0 = bm + wm + mi * 16 + tq;
            if (r0 < NN) {
                float2 v = make_float2(acc[mi][ni][0] + b0, acc[mi][ni][1] + b1);
                *(float2*)(out + (size_t)r0 * 256 + cc) = v;
            }
            int r1 = r0 + 8;
            if (r1 < NN) {
                float2 v = make_float2(acc[mi][ni][2] + b0, acc[mi][ni][3] + b1);
                *(float2*)(out + (size_t)r1 * 256 + cc) = v;
            }
        }
    }
}

// ---------------- launch ----------------
extern "C" void kernel_launch(void* const* d_in, const int* in_sizes, int n_in,
                              void* d_out, int out_size) {
    const float* mean        = (const float*)d_in[0];
    const float* cov         = (const float*)d_in[1];
    const int*   edge_index  = (const int*)  d_in[2];
    const float* W_mean      = (const float*)d_in[3];
    const float* att_src_m   = (const float*)d_in[4];
    const float* att_dst_m   = (const float*)d_in[5];
    const float* bias_mean   = (const float*)d_in[6];
    const float* W_cov       = (const float*)d_in[7];
    const float* att_src_c   = (const float*)d_in[8];
    const float* att_dst_c   = (const float*)d_in[9];
    const float* bias_cov    = (const float*)d_in[10];
    const float* fm_W1       = (const float*)d_in[11];
    const float* fm_b1       = (const float*)d_in[12];
    const float* fm_W2       = (const float*)d_in[13];
    const float* fm_b2       = (const float*)d_in[14];
    const float* fcv_W1      = (const float*)d_in[15];
    const float* fcv_b1      = (const float*)d_in[16];
    const float* fcv_W2      = (const float*)d_in[17];
    const float* fcv_b2      = (const float*)d_in[18];
    float* outp = (float*)d_out;

    cudaFuncSetAttribute(k_mma_cov, cudaFuncAttributeMaxDynamicSharedMemorySize,
                         SH_SMEM_BYTES);

    // phase 1: input-only work (incl. fp16 cov shadow)
    k_combo1<<<6711, 256>>>(fcv_W1, fcv_W2, W_cov, att_src_c, att_dst_c,
                            fm_W1, fm_W2, fm_b1, fm_b2, bias_mean, W_mean,
                            att_src_m, att_dst_m, cov);

    // phase 2: logits, hist, mean proj, Wfold, bias
    k_combo2<<<12757, 256>>>(mean, cov, edge_index, W_cov,
                             bias_cov, fcv_b1, fcv_W2, fcv_b2);

    // phase 3-4: CSR finalize; scatter emits per-edge exp numerators
    k_scan<<<1, 1024>>>();
    k_scatter<<<(ETOT + 255) / 256, 256>>>(edge_index);

    // phase 5: fused aggregation (fp16 gather, z written as fp16)
    k_agg_fused<<<NN, 320>>>(outp);

    // phase 6: fp16 tensor-core projection of z (R13-proven BK=32)
    dim3 gg(2, (NN + 127) / 128);
    k_mma_cov<<<gg, 256, SH_SMEM_BYTES>>>(outp + (size_t)NN * 16);
}